// round 14
// baseline (speedup 1.0000x reference)
#include <cuda_runtime.h>
#include <cuda_bf16.h>
#include <math.h>

// ---------------------------------------------------------------------------
// GATModel: 3x GATConv (heads=1) + max/sum/mean pooling + dense MLP tail.
// N=50000 nodes, E=800000 edges (+N self-loops), G=64 graphs, F_IN=128, OUT=128.
//
// Strategy:
//  - Build CSR (by dst) once per call, reuse for all 3 GAT layers.
//  - Per layer: fp32 GEMM (shared-x, register-blocked), per-node attention
//    dots, then warp-per-dst-node aggregation (max pass + fused exp-sum /
//    weighted-h-sum pass; no atomics).
//  - Pooling: block-per-graph using graph start offsets (batch is sorted).
//  - Dense tail: block-per-graph-row micro GEMMs.
// All scratch in __device__ globals (no allocation). Everything on the
// default stream => graph-capturable.
// ---------------------------------------------------------------------------

#define N_NODES 50000
#define N_EDGES 800000
#define EL      (N_EDGES + N_NODES)
#define G_GRAPHS 64

__device__ float d_bufA[(size_t)N_NODES * 256];
__device__ float d_bufB[(size_t)N_NODES * 256];
__device__ float d_as[N_NODES];
__device__ float d_ad[N_NODES];
__device__ int   d_deg[N_NODES];
__device__ int   d_rowptr[N_NODES + 1];
__device__ int   d_cursor[N_NODES];
__device__ int   d_csrc[EL];
__device__ int   d_gstart[G_GRAPHS + 1];
__device__ float d_z0[G_GRAPHS * 512];
__device__ float d_zA[G_GRAPHS * 512];
__device__ float d_zB[G_GRAPHS * 512];
__device__ float d_x3[G_GRAPHS * 256];

// ----------------------------- CSR construction ----------------------------

__global__ void k_hist(const int* __restrict__ dst, int E, int n, int* __restrict__ deg) {
    int i = blockIdx.x * blockDim.x + threadIdx.x;
    int total = E + n;
    if (i >= total) return;
    int d = (i < E) ? dst[i] : (i - E);   // self-loops appended
    atomicAdd(&deg[d], 1);
}

// Single-block exclusive scan over n (<=50000) ints.
__global__ void k_scan(const int* __restrict__ deg, int* __restrict__ rowptr, int n) {
    const int NTH = 1024;
    __shared__ int ssum[NTH];
    int t = threadIdx.x;
    int L = (n + NTH - 1) / NTH;
    int b0 = t * L;
    int b1 = min(b0 + L, n);
    int s = 0;
    for (int i = b0; i < b1; i++) s += deg[i];
    ssum[t] = s;
    __syncthreads();
    for (int off = 1; off < NTH; off <<= 1) {
        int v = (t >= off) ? ssum[t - off] : 0;
        __syncthreads();
        ssum[t] += v;
        __syncthreads();
    }
    int run = (t == 0) ? 0 : ssum[t - 1];
    for (int i = b0; i < b1; i++) { rowptr[i] = run; run += deg[i]; }
    if (t == NTH - 1) rowptr[n] = ssum[NTH - 1];
}

__global__ void k_scatter(const int* __restrict__ src, const int* __restrict__ dst,
                          int E, int n, int* __restrict__ cursor, int* __restrict__ csrc) {
    int i = blockIdx.x * blockDim.x + threadIdx.x;
    int total = E + n;
    if (i >= total) return;
    int s, d;
    if (i < E) { s = src[i]; d = dst[i]; }
    else       { s = d = i - E; }
    int pos = atomicAdd(&cursor[d], 1);
    csrc[pos] = s;
}

// ------------------------------- node GEMM ---------------------------------
// H[n,OUT] = X[n,IN] @ W[IN,OUT]. Block: OUT/FCOLS threads, 16 rows per block.
template <int IN, int OUT, int FCOLS>
__global__ void k_gemm(const float* __restrict__ X, const float* __restrict__ W,
                       float* __restrict__ H, int n) {
    const int ROWS = 16;
    const int TPB  = OUT / FCOLS;
    __shared__ float xs[ROWS * IN];
    int r0 = blockIdx.x * ROWS;
    for (int idx = threadIdx.x; idx < ROWS * IN; idx += TPB) {
        int r = idx / IN;
        int gr = r0 + r;
        xs[idx] = (gr < n) ? X[(size_t)gr * IN + (idx - r * IN)] : 0.f;
    }
    __syncthreads();

    float acc[ROWS][FCOLS];
#pragma unroll
    for (int r = 0; r < ROWS; r++)
#pragma unroll
        for (int c = 0; c < FCOLS; c++) acc[r][c] = 0.f;

    int f0 = threadIdx.x * FCOLS;
    for (int i = 0; i < IN; i++) {
        float w[FCOLS];
        if (FCOLS == 4) {
            float4 wv = *reinterpret_cast<const float4*>(W + (size_t)i * OUT + f0);
            w[0] = wv.x; w[1] = wv.y; w[2] = wv.z; w[3] = wv.w;
        } else {
            float2 wv = *reinterpret_cast<const float2*>(W + (size_t)i * OUT + f0);
            w[0] = wv.x; w[1] = wv.y;
        }
#pragma unroll
        for (int r = 0; r < ROWS; r++) {
            float xv = xs[r * IN + i];
#pragma unroll
            for (int c = 0; c < FCOLS; c++) acc[r][c] += xv * w[c];
        }
    }
#pragma unroll
    for (int r = 0; r < ROWS; r++) {
        int gr = r0 + r;
        if (gr < n) {
#pragma unroll
            for (int c = 0; c < FCOLS; c++)
                H[(size_t)gr * OUT + f0 + c] = acc[r][c];
        }
    }
}

// ------------------------- per-node attention dots --------------------------
__global__ void k_dots(const float* __restrict__ h, const float* __restrict__ asrc,
                       const float* __restrict__ adst, float* __restrict__ as_,
                       float* __restrict__ ad_, int n, int OUT) {
    int warp = (blockIdx.x * blockDim.x + threadIdx.x) >> 5;
    int lane = threadIdx.x & 31;
    if (warp >= n) return;
    const float* hr = h + (size_t)warp * OUT;
    float sa = 0.f, sd = 0.f;
    for (int f = lane; f < OUT; f += 32) {
        float v = hr[f];
        sa += v * asrc[f];
        sd += v * adst[f];
    }
#pragma unroll
    for (int o = 16; o; o >>= 1) {
        sa += __shfl_xor_sync(0xffffffffu, sa, o);
        sd += __shfl_xor_sync(0xffffffffu, sd, o);
    }
    if (lane == 0) { as_[warp] = sa; ad_[warp] = sd; }
}

// ------------------- warp-per-dst softmax aggregation -----------------------
// out[d] = (sum_j exp(e_j - max) * h[src_j]) / (sum_j exp(e_j - max)) + bias
template <int OUT>
__global__ void k_aggr(const float* __restrict__ h, const float* __restrict__ as_,
                       const float* __restrict__ ad_, const int* __restrict__ rowptr,
                       const int* __restrict__ csrc, const float* __restrict__ bias,
                       float* __restrict__ out, int n) {
    int warp = (blockIdx.x * blockDim.x + threadIdx.x) >> 5;
    int lane = threadIdx.x & 31;
    if (warp >= n) return;
    int beg = rowptr[warp], end = rowptr[warp + 1];
    float adn = ad_[warp];

    // pass 1: max of LeakyReLU(e)
    float mx = -3.4e38f;
    for (int j = beg + lane; j < end; j += 32) {
        float e = as_[csrc[j]] + adn;
        e = (e > 0.f) ? e : 0.2f * e;
        mx = fmaxf(mx, e);
    }
#pragma unroll
    for (int o = 16; o; o >>= 1) mx = fmaxf(mx, __shfl_xor_sync(0xffffffffu, mx, o));

    // pass 2: fused exp-sum + weighted h-sum
    const int NF = OUT / 32;
    float acc[NF];
#pragma unroll
    for (int f = 0; f < NF; f++) acc[f] = 0.f;
    float den = 0.f;

    for (int base = beg; base < end; base += 32) {
        int j = base + lane;
        int s = 0;
        float ex = 0.f;
        if (j < end) {
            s = csrc[j];
            float e = as_[s] + adn;
            e = (e > 0.f) ? e : 0.2f * e;
            ex = __expf(e - mx);
        }
        den += ex;
        int cnt = min(32, end - base);
        for (int k = 0; k < cnt; k++) {
            int   ss = __shfl_sync(0xffffffffu, s, k);
            float ww = __shfl_sync(0xffffffffu, ex, k);
            const float* hr = h + (size_t)ss * OUT;
#pragma unroll
            for (int f = 0; f < NF; f++) acc[f] += ww * hr[lane + f * 32];
        }
    }
#pragma unroll
    for (int o = 16; o; o >>= 1) den += __shfl_xor_sync(0xffffffffu, den, o);
    float inv = 1.f / den;  // self-loop guarantees den > 0
#pragma unroll
    for (int f = 0; f < NF; f++)
        out[(size_t)warp * OUT + lane + f * 32] = acc[f] * inv + bias[lane + f * 32];
}

// ------------------------------- pooling ------------------------------------
__global__ void k_gstart(const int* __restrict__ batch, int* __restrict__ gstart,
                         int n, int G) {
    int i = blockIdx.x * blockDim.x + threadIdx.x;
    if (i >= n) return;
    int b = batch[i];
    int bp = (i == 0) ? -1 : batch[i - 1];
    for (int g = bp + 1; g <= b; g++) gstart[g] = i;
    if (i == n - 1)
        for (int g = b + 1; g <= G; g++) gstart[g] = n;
}

// block per graph; 256 threads = 256 features of h3. Writes concat(max,sum)
// into z0 and mean into x3.
__global__ void k_pool(const float* __restrict__ h, const int* __restrict__ gstart,
                       float* __restrict__ z0, float* __restrict__ x3) {
    int g = blockIdx.x;
    int f = threadIdx.x;
    int s = gstart[g], e = gstart[g + 1];
    float mx = -3.4e38f, sm = 0.f;
    for (int i = s; i < e; i++) {
        float v = h[(size_t)i * 256 + f];
        mx = fmaxf(mx, v);
        sm += v;
    }
    float cnt = (float)(e - s);
    z0[g * 512 + f]       = mx;
    z0[g * 512 + 256 + f] = sm;
    x3[g * 256 + f]       = sm / fmaxf(cnt, 1.0f);
}

// ------------------------------ dense tail ----------------------------------
// act: 0 = none, 1 = relu, 2 = out = mul * sigmoid(acc)
__global__ void k_dense(const float* __restrict__ in, const float* __restrict__ w,
                        const float* __restrict__ b, float* __restrict__ out,
                        int IN, int OUT, int act, const float* __restrict__ mul) {
    __shared__ float s[512];
    int g = blockIdx.x;
    for (int i = threadIdx.x; i < IN; i += blockDim.x) s[i] = in[g * IN + i];
    __syncthreads();
    int f = threadIdx.x;
    if (f < OUT) {
        float acc = b[f];
        for (int i = 0; i < IN; i++) acc += s[i] * w[(size_t)i * OUT + f];
        if (act == 1)      acc = fmaxf(acc, 0.f);
        else if (act == 2) acc = mul[g * OUT + f] * (1.f / (1.f + __expf(-acc)));
        out[g * OUT + f] = acc;
    }
}

// ------------------------------- launcher -----------------------------------

extern "C" void kernel_launch(void* const* d_in, const int* in_sizes, int n_in,
                              void* d_out, int out_size) {
    const float* x      = (const float*)d_in[0];
    const int*   ei     = (const int*)d_in[1];
    const int*   batch  = (const int*)d_in[2];
    const float* W1 = (const float*)d_in[3],  *as1 = (const float*)d_in[4];
    const float* ad1 = (const float*)d_in[5], *b1 = (const float*)d_in[6];
    const float* W2 = (const float*)d_in[7],  *as2 = (const float*)d_in[8];
    const float* ad2 = (const float*)d_in[9], *b2 = (const float*)d_in[10];
    const float* W3 = (const float*)d_in[11], *as3 = (const float*)d_in[12];
    const float* ad3 = (const float*)d_in[13], *b3 = (const float*)d_in[14];
    const float* d1w = (const float*)d_in[15], *d1b = (const float*)d_in[16];
    const float* d2w = (const float*)d_in[17], *d2b = (const float*)d_in[18];
    const float* d3w = (const float*)d_in[19], *d3b = (const float*)d_in[20];
    const float* mw  = (const float*)d_in[21], *mb  = (const float*)d_in[22];
    const float* d4w = (const float*)d_in[23], *d4b = (const float*)d_in[24];
    const float* d5w = (const float*)d_in[25], *d5b = (const float*)d_in[26];
    const float* d6w = (const float*)d_in[27], *d6b = (const float*)d_in[28];
    const float* d7w = (const float*)d_in[29], *d7b = (const float*)d_in[30];
    float* outp = (float*)d_out;

    const int E = in_sizes[1] / 2;          // 800000
    const int n = in_sizes[0] / 128;        // 50000
    const int G = G_GRAPHS;
    const int* src = ei;
    const int* dst = ei + E;

    // scratch pointers
    float *bufA, *bufB, *asv, *adv, *z0, *zA, *zB, *x3;
    int *deg, *rowptr, *cursor, *csrc, *gstart;
    cudaGetSymbolAddress((void**)&bufA,   d_bufA);
    cudaGetSymbolAddress((void**)&bufB,   d_bufB);
    cudaGetSymbolAddress((void**)&asv,    d_as);
    cudaGetSymbolAddress((void**)&adv,    d_ad);
    cudaGetSymbolAddress((void**)&deg,    d_deg);
    cudaGetSymbolAddress((void**)&rowptr, d_rowptr);
    cudaGetSymbolAddress((void**)&cursor, d_cursor);
    cudaGetSymbolAddress((void**)&csrc,   d_csrc);
    cudaGetSymbolAddress((void**)&gstart, d_gstart);
    cudaGetSymbolAddress((void**)&z0,     d_z0);
    cudaGetSymbolAddress((void**)&zA,     d_zA);
    cudaGetSymbolAddress((void**)&zB,     d_zB);
    cudaGetSymbolAddress((void**)&x3,     d_x3);

    // ---- CSR build (once; reused by all 3 layers) ----
    cudaMemsetAsync(deg, 0, (size_t)n * sizeof(int));
    {
        int total = E + n;
        k_hist<<<(total + 255) / 256, 256>>>(dst, E, n, deg);
        k_scan<<<1, 1024>>>(deg, rowptr, n);
        cudaMemcpyAsync(cursor, rowptr, (size_t)n * sizeof(int),
                        cudaMemcpyDeviceToDevice);
        k_scatter<<<(total + 255) / 256, 256>>>(src, dst, E, n, cursor, csrc);
    }

    int gemm_grid  = (n + 15) / 16;
    int warp_grid  = (n * 32 + 255) / 256;   // warp-per-node kernels

    // ---- GAT layer 1: 128 -> 64 ----
    k_gemm<128, 64, 2><<<gemm_grid, 32>>>(x, W1, bufA, n);
    k_dots<<<warp_grid, 256>>>(bufA, as1, ad1, asv, adv, n, 64);
    k_aggr<64><<<warp_grid, 256>>>(bufA, asv, adv, rowptr, csrc, b1, bufB, n);

    // ---- GAT layer 2: 64 -> 128 ----
    k_gemm<64, 128, 4><<<gemm_grid, 32>>>(bufB, W2, bufA, n);
    k_dots<<<warp_grid, 256>>>(bufA, as2, ad2, asv, adv, n, 128);
    k_aggr<128><<<warp_grid, 256>>>(bufA, asv, adv, rowptr, csrc, b2, bufB, n);

    // ---- GAT layer 3: 128 -> 256 ----
    k_gemm<128, 256, 4><<<gemm_grid, 64>>>(bufB, W3, bufA, n);
    k_dots<<<warp_grid, 256>>>(bufA, as3, ad3, asv, adv, n, 256);
    k_aggr<256><<<warp_grid, 256>>>(bufA, asv, adv, rowptr, csrc, b3, bufB, n);

    // ---- pooling ----
    k_gstart<<<(n + 255) / 256, 256>>>(batch, gstart, n, G);
    k_pool<<<G, 256>>>(bufB, gstart, z0, x3);

    // ---- dense tail ----
    k_dense<<<G, 256>>>(z0, d1w, d1b, zA, 512, 256, 1, nullptr);  // z1
    k_dense<<<G, 128>>>(zA, d2w, d2b, zB, 256, 128, 1, nullptr);  // z2
    k_dense<<<G,  64>>>(zB, d3w, d3b, zA, 128,  64, 1, nullptr);  // z3
    k_dense<<<G,  64>>>(x3, mw,  mb,  zB, 256,  64, 2, zA);       // z3 * sigmoid(gate)
    k_dense<<<G,  64>>>(zB, d4w, d4b, zA,  64,  64, 1, nullptr);  // z4
    k_dense<<<G, 128>>>(zA, d5w, d5b, zB,  64, 128, 1, nullptr);  // z5
    k_dense<<<G, 256>>>(zB, d6w, d6b, zA, 128, 256, 1, nullptr);  // z6
    k_dense<<<G, 128>>>(zA, d7w, d7b, outp, 256, 128, 0, nullptr);// out
}

// round 15
// speedup vs baseline: 1.0199x; 1.0199x over previous
#include <cuda_runtime.h>
#include <cuda_bf16.h>
#include <math.h>

// ---------------------------------------------------------------------------
// GATModel: 3x GATConv (heads=1) + max/sum/mean pooling + dense MLP tail.
// N=50000 nodes, E=800000 edges (+N self-loops), G=64 graphs, F_IN=128, OUT=128.
//
// Strategy:
//  - Build CSR (by dst) once per call, reuse for all 3 GAT layers.
//  - Per layer: fp32 GEMM (shared-x, register-blocked), per-node attention
//    dots, then warp-per-dst-node aggregation (max pass + fused exp-sum /
//    weighted-h-sum pass; no atomics).
//  - Pooling: block-per-graph using graph start offsets (batch is sorted).
//  - Dense tail: block-per-graph-row micro GEMMs.
// All scratch in __device__ globals (no allocation). Everything on the
// default stream => graph-capturable.
// ---------------------------------------------------------------------------

#define N_NODES 50000
#define N_EDGES 800000
#define EL      (N_EDGES + N_NODES)
#define G_GRAPHS 64

__device__ float d_bufA[(size_t)N_NODES * 256];
__device__ float d_bufB[(size_t)N_NODES * 256];
__device__ float d_as[N_NODES];
__device__ float d_ad[N_NODES];
__device__ int   d_deg[N_NODES];
__device__ int   d_rowptr[N_NODES + 1];
__device__ int   d_cursor[N_NODES];
__device__ int   d_csrc[EL];
__device__ int   d_gstart[G_GRAPHS + 1];
__device__ float d_z0[G_GRAPHS * 512];
__device__ float d_zA[G_GRAPHS * 512];
__device__ float d_zB[G_GRAPHS * 512];
__device__ float d_x3[G_GRAPHS * 256];

// ----------------------------- CSR construction ----------------------------

__global__ void k_hist(const int* __restrict__ dst, int E, int n, int* __restrict__ deg) {
    int i = blockIdx.x * blockDim.x + threadIdx.x;
    int total = E + n;
    if (i >= total) return;
    int d = (i < E) ? dst[i] : (i - E);   // self-loops appended
    atomicAdd(&deg[d], 1);
}

// Single-block exclusive scan over n (<=50000) ints.
__global__ void k_scan(const int* __restrict__ deg, int* __restrict__ rowptr, int n) {
    const int NTH = 1024;
    __shared__ int ssum[NTH];
    int t = threadIdx.x;
    int L = (n + NTH - 1) / NTH;
    int b0 = t * L;
    int b1 = min(b0 + L, n);
    int s = 0;
    for (int i = b0; i < b1; i++) s += deg[i];
    ssum[t] = s;
    __syncthreads();
    for (int off = 1; off < NTH; off <<= 1) {
        int v = (t >= off) ? ssum[t - off] : 0;
        __syncthreads();
        ssum[t] += v;
        __syncthreads();
    }
    int run = (t == 0) ? 0 : ssum[t - 1];
    for (int i = b0; i < b1; i++) { rowptr[i] = run; run += deg[i]; }
    if (t == NTH - 1) rowptr[n] = ssum[NTH - 1];
}

__global__ void k_scatter(const int* __restrict__ src, const int* __restrict__ dst,
                          int E, int n, int* __restrict__ cursor, int* __restrict__ csrc) {
    int i = blockIdx.x * blockDim.x + threadIdx.x;
    int total = E + n;
    if (i >= total) return;
    int s, d;
    if (i < E) { s = src[i]; d = dst[i]; }
    else       { s = d = i - E; }
    int pos = atomicAdd(&cursor[d], 1);
    csrc[pos] = s;
}

// ------------------------------- node GEMM ---------------------------------
// H[n,OUT] = X[n,IN] @ W[IN,OUT]. Block: OUT/FCOLS threads, 16 rows per block.
template <int IN, int OUT, int FCOLS>
__global__ void k_gemm(const float* __restrict__ X, const float* __restrict__ W,
                       float* __restrict__ H, int n) {
    const int ROWS = 16;
    const int TPB  = OUT / FCOLS;
    __shared__ float xs[ROWS * IN];
    int r0 = blockIdx.x * ROWS;
    for (int idx = threadIdx.x; idx < ROWS * IN; idx += TPB) {
        int r = idx / IN;
        int gr = r0 + r;
        xs[idx] = (gr < n) ? X[(size_t)gr * IN + (idx - r * IN)] : 0.f;
    }
    __syncthreads();

    float acc[ROWS][FCOLS];
#pragma unroll
    for (int r = 0; r < ROWS; r++)
#pragma unroll
        for (int c = 0; c < FCOLS; c++) acc[r][c] = 0.f;

    int f0 = threadIdx.x * FCOLS;
    for (int i = 0; i < IN; i++) {
        float w[FCOLS];
        if (FCOLS == 4) {
            float4 wv = *reinterpret_cast<const float4*>(W + (size_t)i * OUT + f0);
            w[0] = wv.x; w[1] = wv.y; w[2] = wv.z; w[3] = wv.w;
        } else {
            float2 wv = *reinterpret_cast<const float2*>(W + (size_t)i * OUT + f0);
            w[0] = wv.x; w[1] = wv.y;
        }
#pragma unroll
        for (int r = 0; r < ROWS; r++) {
            float xv = xs[r * IN + i];
#pragma unroll
            for (int c = 0; c < FCOLS; c++) acc[r][c] += xv * w[c];
        }
    }
#pragma unroll
    for (int r = 0; r < ROWS; r++) {
        int gr = r0 + r;
        if (gr < n) {
#pragma unroll
            for (int c = 0; c < FCOLS; c++)
                H[(size_t)gr * OUT + f0 + c] = acc[r][c];
        }
    }
}

// ------------------------- per-node attention dots --------------------------
__global__ void k_dots(const float* __restrict__ h, const float* __restrict__ asrc,
                       const float* __restrict__ adst, float* __restrict__ as_,
                       float* __restrict__ ad_, int n, int OUT) {
    int warp = (blockIdx.x * blockDim.x + threadIdx.x) >> 5;
    int lane = threadIdx.x & 31;
    if (warp >= n) return;
    const float* hr = h + (size_t)warp * OUT;
    float sa = 0.f, sd = 0.f;
    for (int f = lane; f < OUT; f += 32) {
        float v = hr[f];
        sa += v * asrc[f];
        sd += v * adst[f];
    }
#pragma unroll
    for (int o = 16; o; o >>= 1) {
        sa += __shfl_xor_sync(0xffffffffu, sa, o);
        sd += __shfl_xor_sync(0xffffffffu, sd, o);
    }
    if (lane == 0) { as_[warp] = sa; ad_[warp] = sd; }
}

// ------------------- warp-per-dst softmax aggregation -----------------------
// out[d] = (sum_j exp(e_j - max) * h[src_j]) / (sum_j exp(e_j - max)) + bias
template <int OUT>
__global__ void k_aggr(const float* __restrict__ h, const float* __restrict__ as_,
                       const float* __restrict__ ad_, const int* __restrict__ rowptr,
                       const int* __restrict__ csrc, const float* __restrict__ bias,
                       float* __restrict__ out, int n) {
    int warp = (blockIdx.x * blockDim.x + threadIdx.x) >> 5;
    int lane = threadIdx.x & 31;
    if (warp >= n) return;
    int beg = rowptr[warp], end = rowptr[warp + 1];
    float adn = ad_[warp];

    // pass 1: max of LeakyReLU(e)
    float mx = -3.4e38f;
    for (int j = beg + lane; j < end; j += 32) {
        float e = as_[csrc[j]] + adn;
        e = (e > 0.f) ? e : 0.2f * e;
        mx = fmaxf(mx, e);
    }
#pragma unroll
    for (int o = 16; o; o >>= 1) mx = fmaxf(mx, __shfl_xor_sync(0xffffffffu, mx, o));

    // pass 2: fused exp-sum + weighted h-sum
    const int NF = OUT / 32;
    float acc[NF];
#pragma unroll
    for (int f = 0; f < NF; f++) acc[f] = 0.f;
    float den = 0.f;

    for (int base = beg; base < end; base += 32) {
        int j = base + lane;
        int s = 0;
        float ex = 0.f;
        if (j < end) {
            s = csrc[j];
            float e = as_[s] + adn;
            e = (e > 0.f) ? e : 0.2f * e;
            ex = __expf(e - mx);
        }
        den += ex;
        int cnt = min(32, end - base);
        for (int k = 0; k < cnt; k++) {
            int   ss = __shfl_sync(0xffffffffu, s, k);
            float ww = __shfl_sync(0xffffffffu, ex, k);
            const float* hr = h + (size_t)ss * OUT;
#pragma unroll
            for (int f = 0; f < NF; f++) acc[f] += ww * hr[lane + f * 32];
        }
    }
#pragma unroll
    for (int o = 16; o; o >>= 1) den += __shfl_xor_sync(0xffffffffu, den, o);
    float inv = 1.f / den;  // self-loop guarantees den > 0
#pragma unroll
    for (int f = 0; f < NF; f++)
        out[(size_t)warp * OUT + lane + f * 32] = acc[f] * inv + bias[lane + f * 32];
}

// ------------------------------- pooling ------------------------------------
__global__ void k_gstart(const int* __restrict__ batch, int* __restrict__ gstart,
                         int n, int G) {
    int i = blockIdx.x * blockDim.x + threadIdx.x;
    if (i >= n) return;
    int b = batch[i];
    int bp = (i == 0) ? -1 : batch[i - 1];
    for (int g = bp + 1; g <= b; g++) gstart[g] = i;
    if (i == n - 1)
        for (int g = b + 1; g <= G; g++) gstart[g] = n;
}

// block per graph; 256 threads = 256 features of h3. Writes concat(max,sum)
// into z0 and mean into x3.
__global__ void k_pool(const float* __restrict__ h, const int* __restrict__ gstart,
                       float* __restrict__ z0, float* __restrict__ x3) {
    int g = blockIdx.x;
    int f = threadIdx.x;
    int s = gstart[g], e = gstart[g + 1];
    float mx = -3.4e38f, sm = 0.f;
    for (int i = s; i < e; i++) {
        float v = h[(size_t)i * 256 + f];
        mx = fmaxf(mx, v);
        sm += v;
    }
    float cnt = (float)(e - s);
    z0[g * 512 + f]       = mx;
    z0[g * 512 + 256 + f] = sm;
    x3[g * 256 + f]       = sm / fmaxf(cnt, 1.0f);
}

// ------------------------------ dense tail ----------------------------------
// act: 0 = none, 1 = relu, 2 = out = mul * sigmoid(acc)
__global__ void k_dense(const float* __restrict__ in, const float* __restrict__ w,
                        const float* __restrict__ b, float* __restrict__ out,
                        int IN, int OUT, int act, const float* __restrict__ mul) {
    __shared__ float s[512];
    int g = blockIdx.x;
    for (int i = threadIdx.x; i < IN; i += blockDim.x) s[i] = in[g * IN + i];
    __syncthreads();
    int f = threadIdx.x;
    if (f < OUT) {
        float acc = b[f];
        for (int i = 0; i < IN; i++) acc += s[i] * w[(size_t)i * OUT + f];
        if (act == 1)      acc = fmaxf(acc, 0.f);
        else if (act == 2) acc = mul[g * OUT + f] * (1.f / (1.f + __expf(-acc)));
        out[g * OUT + f] = acc;
    }
}

// ------------------------------- launcher -----------------------------------

extern "C" void kernel_launch(void* const* d_in, const int* in_sizes, int n_in,
                              void* d_out, int out_size) {
    const float* x      = (const float*)d_in[0];
    const int*   ei     = (const int*)d_in[1];
    const int*   batch  = (const int*)d_in[2];
    const float* W1 = (const float*)d_in[3],  *as1 = (const float*)d_in[4];
    const float* ad1 = (const float*)d_in[5], *b1 = (const float*)d_in[6];
    const float* W2 = (const float*)d_in[7],  *as2 = (const float*)d_in[8];
    const float* ad2 = (const float*)d_in[9], *b2 = (const float*)d_in[10];
    const float* W3 = (const float*)d_in[11], *as3 = (const float*)d_in[12];
    const float* ad3 = (const float*)d_in[13], *b3 = (const float*)d_in[14];
    const float* d1w = (const float*)d_in[15], *d1b = (const float*)d_in[16];
    const float* d2w = (const float*)d_in[17], *d2b = (const float*)d_in[18];
    const float* d3w = (const float*)d_in[19], *d3b = (const float*)d_in[20];
    const float* mw  = (const float*)d_in[21], *mb  = (const float*)d_in[22];
    const float* d4w = (const float*)d_in[23], *d4b = (const float*)d_in[24];
    const float* d5w = (const float*)d_in[25], *d5b = (const float*)d_in[26];
    const float* d6w = (const float*)d_in[27], *d6b = (const float*)d_in[28];
    const float* d7w = (const float*)d_in[29], *d7b = (const float*)d_in[30];
    float* outp = (float*)d_out;

    const int E = in_sizes[1] / 2;          // 800000
    const int n = in_sizes[0] / 128;        // 50000
    const int G = G_GRAPHS;
    const int* src = ei;
    const int* dst = ei + E;

    // scratch pointers
    float *bufA, *bufB, *asv, *adv, *z0, *zA, *zB, *x3;
    int *deg, *rowptr, *cursor, *csrc, *gstart;
    cudaGetSymbolAddress((void**)&bufA,   d_bufA);
    cudaGetSymbolAddress((void**)&bufB,   d_bufB);
    cudaGetSymbolAddress((void**)&asv,    d_as);
    cudaGetSymbolAddress((void**)&adv,    d_ad);
    cudaGetSymbolAddress((void**)&deg,    d_deg);
    cudaGetSymbolAddress((void**)&rowptr, d_rowptr);
    cudaGetSymbolAddress((void**)&cursor, d_cursor);
    cudaGetSymbolAddress((void**)&csrc,   d_csrc);
    cudaGetSymbolAddress((void**)&gstart, d_gstart);
    cudaGetSymbolAddress((void**)&z0,     d_z0);
    cudaGetSymbolAddress((void**)&zA,     d_zA);
    cudaGetSymbolAddress((void**)&zB,     d_zB);
    cudaGetSymbolAddress((void**)&x3,     d_x3);

    // ---- CSR build (once; reused by all 3 layers) ----
    cudaMemsetAsync(deg, 0, (size_t)n * sizeof(int));
    {
        int total = E + n;
        k_hist<<<(total + 255) / 256, 256>>>(dst, E, n, deg);
        k_scan<<<1, 1024>>>(deg, rowptr, n);
        cudaMemcpyAsync(cursor, rowptr, (size_t)n * sizeof(int),
                        cudaMemcpyDeviceToDevice);
        k_scatter<<<(total + 255) / 256, 256>>>(src, dst, E, n, cursor, csrc);
    }

    int gemm_grid  = (n + 15) / 16;
    int warp_grid  = (n * 32 + 255) / 256;   // warp-per-node kernels

    // ---- GAT layer 1: 128 -> 64 ----
    k_gemm<128, 64, 2><<<gemm_grid, 32>>>(x, W1, bufA, n);
    k_dots<<<warp_grid, 256>>>(bufA, as1, ad1, asv, adv, n, 64);
    k_aggr<64><<<warp_grid, 256>>>(bufA, asv, adv, rowptr, csrc, b1, bufB, n);

    // ---- GAT layer 2: 64 -> 128 ----
    k_gemm<64, 128, 4><<<gemm_grid, 32>>>(bufB, W2, bufA, n);
    k_dots<<<warp_grid, 256>>>(bufA, as2, ad2, asv, adv, n, 128);
    k_aggr<128><<<warp_grid, 256>>>(bufA, asv, adv, rowptr, csrc, b2, bufB, n);

    // ---- GAT layer 3: 128 -> 256 ----
    k_gemm<128, 256, 4><<<gemm_grid, 64>>>(bufB, W3, bufA, n);
    k_dots<<<warp_grid, 256>>>(bufA, as3, ad3, asv, adv, n, 256);
    k_aggr<256><<<warp_grid, 256>>>(bufA, asv, adv, rowptr, csrc, b3, bufB, n);

    // ---- pooling ----
    k_gstart<<<(n + 255) / 256, 256>>>(batch, gstart, n, G);
    k_pool<<<G, 256>>>(bufB, gstart, z0, x3);

    // ---- dense tail ----
    k_dense<<<G, 256>>>(z0, d1w, d1b, zA, 512, 256, 1, nullptr);  // z1
    k_dense<<<G, 128>>>(zA, d2w, d2b, zB, 256, 128, 1, nullptr);  // z2
    k_dense<<<G,  64>>>(zB, d3w, d3b, zA, 128,  64, 1, nullptr);  // z3
    k_dense<<<G,  64>>>(x3, mw,  mb,  zB, 256,  64, 2, zA);       // z3 * sigmoid(gate)
    k_dense<<<G,  64>>>(zB, d4w, d4b, zA,  64,  64, 1, nullptr);  // z4
    k_dense<<<G, 128>>>(zA, d5w, d5b, zB,  64, 128, 1, nullptr);  // z5
    k_dense<<<G, 256>>>(zB, d6w, d6b, zA, 128, 256, 1, nullptr);  // z6
    k_dense<<<G, 128>>>(zA, d7w, d7b, outp, 256, 128, 0, nullptr);// out
}